// round 15
// baseline (speedup 1.0000x reference)
#include <cuda_runtime.h>
#include <cuda_fp16.h>
#include <cstdint>

#define NLVL  10
#define EMB   64
#define NROWS 10002   // 2 zero rows + 10000 table rows

__device__ __align__(16)  float  g_ew[12];             // raw exp(w[l]); [10],[11]=0
__device__ __align__(16)  float  g_al[12];             // prenormalized alphas
__device__ __align__(256) __half g_tab[NROWS * EMB];   // fp16 concept_emb_cat, row=128B

// Convert table fp32->fp16 (rows shifted by +2, rows 0/1 zeroed), exp(w),
// and prenormalized all-available alphas. Early PDL trigger per block.
__global__ void conv_kernel(const float* __restrict__ emb,
                            const float* __restrict__ w, int n16) {
    const int tid = blockIdx.x * blockDim.x + threadIdx.x;
    if (blockIdx.x == 0 && threadIdx.x == 0) {
        float e[NLVL], s = 0.0f;
#pragma unroll
        for (int l = 0; l < NLVL; l++) { e[l] = __expf(w[l]); s += e[l]; }
        const float inv = __frcp_rn(s);
#pragma unroll
        for (int l = 0; l < NLVL; l++) { g_ew[l] = e[l]; g_al[l] = e[l] * inv; }
        g_ew[10] = g_ew[11] = 0.0f;
        g_al[10] = g_al[11] = 0.0f;
    }
    if (blockIdx.x == 0 && threadIdx.x < 16)   // zero rows 0,1: 256B = 16 x 16B
        reinterpret_cast<uint4*>(g_tab)[threadIdx.x] = make_uint4(0u,0u,0u,0u);
    if (tid < n16) {
        const float4* src = reinterpret_cast<const float4*>(emb) + (size_t)tid * 4;
        float4 v[4];
#pragma unroll
        for (int k = 0; k < 4; k++) v[k] = src[k];   // 4 independent LDG.128
        uint4* dst = reinterpret_cast<uint4*>(g_tab + 2 * EMB) + (size_t)tid * 2;
#pragma unroll
        for (int k = 0; k < 2; k++) {
            const __half2 h0 = __floats2half2_rn(v[2*k].x,   v[2*k].y);
            const __half2 h1 = __floats2half2_rn(v[2*k].z,   v[2*k].w);
            const __half2 h2 = __floats2half2_rn(v[2*k+1].x, v[2*k+1].y);
            const __half2 h3 = __floats2half2_rn(v[2*k+1].z, v[2*k+1].w);
            uint4 p;
            p.x = *reinterpret_cast<const unsigned*>(&h0);
            p.y = *reinterpret_cast<const unsigned*>(&h1);
            p.z = *reinterpret_cast<const unsigned*>(&h2);
            p.w = *reinterpret_cast<const unsigned*>(&h3);
            dst[k] = p;
        }
    }
#if __CUDA_ARCH__ >= 900
    __threadfence();
    cudaTriggerProgrammaticLaunchCompletion();
#endif
}

// 8 lanes/token (lane qi covers cols [8*qi, 8*qi+8) = 16B fp16), 256-thread
// CTAs, cp.async gathers in two commit groups. Fast path: all levels
// available (idx != -2, always true for this data) -> use prenormalized
// alphas, no per-token softmax. Slow path keeps full generality.
__global__ __launch_bounds__(256, 5) void kcroute_kernel(
    const int* __restrict__ croutes,   // [ntok, NLVL]
    float*     __restrict__ out,       // [ntok, EMB]
    int ntok)
{
    __shared__ __half stab[8][4][NLVL][EMB];   // 5 KB/warp, 40 KB/block

    const int tid = threadIdx.x;
    const int wid = tid >> 5;
    const int tw  = (tid >> 3) & 3;
    const int qi  = tid & 7;
    int tok = blockIdx.x * 32 + (tid >> 3);
    const bool valid = (tok < ntok);
    if (!valid) tok = 0;

    // Indices: independent of conv output -> before the dependency sync.
    const int2* cr = reinterpret_cast<const int2*>(croutes + (size_t)tok * NLVL);
    const int2 i0 = __ldg(cr + 0), i1 = __ldg(cr + 1), i2 = __ldg(cr + 2),
               i3 = __ldg(cr + 3), i4 = __ldg(cr + 4);
    const int idx[NLVL] = { i0.x, i0.y, i1.x, i1.y, i2.x, i2.y,
                            i3.x, i3.y, i4.x, i4.y };

#if __CUDA_ARCH__ >= 900
    cudaGridDependencySynchronize();
#endif

    uint32_t sbase;
    {
        const void* p0 = &stab[wid][tw][0][qi * 8];
        asm("{ .reg .u64 t; cvta.to.shared.u64 t, %1; cvt.u32.u64 %0, t; }"
            : "=r"(sbase) : "l"(p0));
    }
    // Group A: levels 0-4 (.ca -> table lines can hit/populate L1).
#pragma unroll
    for (int l = 0; l < 5; l++) {
        const __half* gp = g_tab + ((size_t)(idx[l] + 2)) * EMB + qi * 8;
        asm volatile("cp.async.ca.shared.global [%0], [%1], 16;"
                     :: "r"(sbase + l * (EMB * 2)), "l"(gp));
    }
    asm volatile("cp.async.commit_group;");
    // Group B: levels 5-9.
#pragma unroll
    for (int l = 5; l < NLVL; l++) {
        const __half* gp = g_tab + ((size_t)(idx[l] + 2)) * EMB + qi * 8;
        asm volatile("cp.async.ca.shared.global [%0], [%1], 16;"
                     :: "r"(sbase + l * (EMB * 2)), "l"(gp));
    }
    asm volatile("cp.async.commit_group;");

    // Alphas: fast path uses prenormalized g_al (all levels available).
    // Uniform slow path only if some idx == -2 (never for this dataset).
    bool bad = false;
#pragma unroll
    for (int l = 0; l < NLVL; l++) bad |= (idx[l] == -2);

    const float4 aa = *reinterpret_cast<const float4*>(&g_al[0]);
    const float4 ab = *reinterpret_cast<const float4*>(&g_al[4]);
    const float2 ac = *reinterpret_cast<const float2*>(&g_al[8]);
    float al[NLVL] = { aa.x, aa.y, aa.z, aa.w,
                       ab.x, ab.y, ab.z, ab.w, ac.x, ac.y };
    if (__builtin_expect(bad, 0)) {
        const float4 ea = *reinterpret_cast<const float4*>(&g_ew[0]);
        const float4 eb = *reinterpret_cast<const float4*>(&g_ew[4]);
        const float2 ec = *reinterpret_cast<const float2*>(&g_ew[8]);
        const float e[NLVL] = { ea.x, ea.y, ea.z, ea.w,
                                eb.x, eb.y, eb.z, eb.w, ec.x, ec.y };
        float s = 0.0f;
#pragma unroll
        for (int l = 0; l < NLVL; l++) s += (idx[l] != -2) ? e[l] : 0.0f;
        const float inv = (s > 0.0f) ? __frcp_rn(s) : 0.0f;
#pragma unroll
        for (int l = 0; l < NLVL; l++)
            al[l] = (idx[l] != -2) ? e[l] * inv : 0.0f;
    }

    float acc[8] = {0.f,0.f,0.f,0.f,0.f,0.f,0.f,0.f};

    asm volatile("cp.async.wait_group 1;");
    __syncwarp();
#pragma unroll
    for (int l = 0; l < 5; l++) {
        const uint4 v = *reinterpret_cast<const uint4*>(&stab[wid][tw][l][qi * 8]);
        const float2 a = __half22float2(*reinterpret_cast<const __half2*>(&v.x));
        const float2 b = __half22float2(*reinterpret_cast<const __half2*>(&v.y));
        const float2 c = __half22float2(*reinterpret_cast<const __half2*>(&v.z));
        const float2 d = __half22float2(*reinterpret_cast<const __half2*>(&v.w));
        acc[0] = fmaf(al[l], a.x, acc[0]);
        acc[1] = fmaf(al[l], a.y, acc[1]);
        acc[2] = fmaf(al[l], b.x, acc[2]);
        acc[3] = fmaf(al[l], b.y, acc[3]);
        acc[4] = fmaf(al[l], c.x, acc[4]);
        acc[5] = fmaf(al[l], c.y, acc[5]);
        acc[6] = fmaf(al[l], d.x, acc[6]);
        acc[7] = fmaf(al[l], d.y, acc[7]);
    }

    asm volatile("cp.async.wait_group 0;");
    __syncwarp();
#pragma unroll
    for (int l = 5; l < NLVL; l++) {
        const uint4 v = *reinterpret_cast<const uint4*>(&stab[wid][tw][l][qi * 8]);
        const float2 a = __half22float2(*reinterpret_cast<const __half2*>(&v.x));
        const float2 b = __half22float2(*reinterpret_cast<const __half2*>(&v.y));
        const float2 c = __half22float2(*reinterpret_cast<const __half2*>(&v.z));
        const float2 d = __half22float2(*reinterpret_cast<const __half2*>(&v.w));
        acc[0] = fmaf(al[l], a.x, acc[0]);
        acc[1] = fmaf(al[l], a.y, acc[1]);
        acc[2] = fmaf(al[l], b.x, acc[2]);
        acc[3] = fmaf(al[l], b.y, acc[3]);
        acc[4] = fmaf(al[l], c.x, acc[4]);
        acc[5] = fmaf(al[l], c.y, acc[5]);
        acc[6] = fmaf(al[l], d.x, acc[6]);
        acc[7] = fmaf(al[l], d.y, acc[7]);
    }

    if (valid) {
        float* op = out + (size_t)tok * EMB + qi * 8;
        *reinterpret_cast<float4*>(op) =
            make_float4(acc[0], acc[1], acc[2], acc[3]);
        *reinterpret_cast<float4*>(op + 4) =
            make_float4(acc[4], acc[5], acc[6], acc[7]);
    }
}

extern "C" void kernel_launch(void* const* d_in, const int* in_sizes, int n_in,
                              void* d_out, int out_size) {
    const int*   croutes = (const int*)d_in[0];
    // d_in[1] (tailcs) unused by the reference computation.
    const float* emb     = (const float*)d_in[2];
    const float* w       = (const float*)d_in[3];
    float*       out     = (float*)d_out;

    const int ntok = in_sizes[1];                 // B * S
    const int n16  = in_sizes[2] / 16;            // table 16-float chunks
    conv_kernel<<<(n16 + 255) / 256, 256>>>(emb, w, n16);

    const int blocks = (ntok + 31) / 32;          // 32 tokens per 256-thread block

    cudaLaunchConfig_t cfg = {};
    cfg.gridDim  = dim3((unsigned)blocks, 1, 1);
    cfg.blockDim = dim3(256, 1, 1);
    cudaLaunchAttribute attr[1];
    attr[0].id = cudaLaunchAttributeProgrammaticStreamSerialization;
    attr[0].val.programmaticStreamSerializationAllowed = 1;
    cfg.attrs    = attr;
    cfg.numAttrs = 1;
    cudaError_t err = cudaLaunchKernelEx(&cfg, kcroute_kernel, croutes, out, ntok);
    if (err != cudaSuccess) {
        kcroute_kernel<<<blocks, 256>>>(croutes, out, ntok);
    }
}

// round 16
// speedup vs baseline: 1.1555x; 1.1555x over previous
#include <cuda_runtime.h>
#include <cuda_fp16.h>
#include <cstdint>

#define NLVL  10
#define EMB   64
#define NROWS 10002   // 2 zero rows + 10000 table rows

__device__ __align__(16)  float  g_ew[12];             // raw exp(w[l]); [10],[11]=0
__device__ __align__(16)  float  g_al[12];             // prenormalized alphas
__device__ __align__(256) __half g_tab[NROWS * EMB];   // fp16 concept_emb_cat, row=128B

// Convert table fp32->fp16 (rows shifted by +2, rows 0/1 zeroed), exp(w),
// and prenormalized all-available alphas. Early PDL trigger per block.
__global__ void conv_kernel(const float* __restrict__ emb,
                            const float* __restrict__ w, int n16) {
    const int tid = blockIdx.x * blockDim.x + threadIdx.x;
    if (blockIdx.x == 0 && threadIdx.x == 0) {
        float e[NLVL], s = 0.0f;
#pragma unroll
        for (int l = 0; l < NLVL; l++) { e[l] = __expf(w[l]); s += e[l]; }
        const float inv = __frcp_rn(s);
#pragma unroll
        for (int l = 0; l < NLVL; l++) { g_ew[l] = e[l]; g_al[l] = e[l] * inv; }
        g_ew[10] = g_ew[11] = 0.0f;
        g_al[10] = g_al[11] = 0.0f;
    }
    if (blockIdx.x == 0 && threadIdx.x < 16)   // zero rows 0,1: 256B = 16 x 16B
        reinterpret_cast<uint4*>(g_tab)[threadIdx.x] = make_uint4(0u,0u,0u,0u);
    if (tid < n16) {
        const float4* src = reinterpret_cast<const float4*>(emb) + (size_t)tid * 4;
        float4 v[4];
#pragma unroll
        for (int k = 0; k < 4; k++) v[k] = src[k];   // 4 independent LDG.128
        uint4* dst = reinterpret_cast<uint4*>(g_tab + 2 * EMB) + (size_t)tid * 2;
#pragma unroll
        for (int k = 0; k < 2; k++) {
            const __half2 h0 = __floats2half2_rn(v[2*k].x,   v[2*k].y);
            const __half2 h1 = __floats2half2_rn(v[2*k].z,   v[2*k].w);
            const __half2 h2 = __floats2half2_rn(v[2*k+1].x, v[2*k+1].y);
            const __half2 h3 = __floats2half2_rn(v[2*k+1].z, v[2*k+1].w);
            uint4 p;
            p.x = *reinterpret_cast<const unsigned*>(&h0);
            p.y = *reinterpret_cast<const unsigned*>(&h1);
            p.z = *reinterpret_cast<const unsigned*>(&h2);
            p.w = *reinterpret_cast<const unsigned*>(&h3);
            dst[k] = p;
        }
    }
#if __CUDA_ARCH__ >= 900
    __threadfence();
    cudaTriggerProgrammaticLaunchCompletion();
#endif
}

// 8 lanes/token (lane qi covers cols [8*qi, 8*qi+8) = 16B fp16), 256-thread
// CTAs, cp.async.cg (L2-direct) gathers in two commit groups. Fast path uses
// prenormalized alphas (all levels available — always true for this data);
// uniform slow path keeps full generality.
__global__ __launch_bounds__(256, 5) void kcroute_kernel(
    const int* __restrict__ croutes,   // [ntok, NLVL]
    float*     __restrict__ out,       // [ntok, EMB]
    int ntok)
{
    __shared__ __half stab[8][4][NLVL][EMB];   // 5 KB/warp, 40 KB/block

    const int tid = threadIdx.x;
    const int wid = tid >> 5;
    const int tw  = (tid >> 3) & 3;
    const int qi  = tid & 7;
    int tok = blockIdx.x * 32 + (tid >> 3);
    const bool valid = (tok < ntok);
    if (!valid) tok = 0;

    // Indices: independent of conv output -> before the dependency sync.
    const int2* cr = reinterpret_cast<const int2*>(croutes + (size_t)tok * NLVL);
    const int2 i0 = __ldg(cr + 0), i1 = __ldg(cr + 1), i2 = __ldg(cr + 2),
               i3 = __ldg(cr + 3), i4 = __ldg(cr + 4);
    const int idx[NLVL] = { i0.x, i0.y, i1.x, i1.y, i2.x, i2.y,
                            i3.x, i3.y, i4.x, i4.y };

#if __CUDA_ARCH__ >= 900
    cudaGridDependencySynchronize();
#endif

    uint32_t sbase;
    {
        const void* p0 = &stab[wid][tw][0][qi * 8];
        asm("{ .reg .u64 t; cvta.to.shared.u64 t, %1; cvt.u32.u64 %0, t; }"
            : "=r"(sbase) : "l"(p0));
    }
    // Group A: levels 0-4 (.cg — L2-direct; .ca measured 3.0us slower in R15).
#pragma unroll
    for (int l = 0; l < 5; l++) {
        const __half* gp = g_tab + ((size_t)(idx[l] + 2)) * EMB + qi * 8;
        asm volatile("cp.async.cg.shared.global [%0], [%1], 16;"
                     :: "r"(sbase + l * (EMB * 2)), "l"(gp));
    }
    asm volatile("cp.async.commit_group;");
    // Group B: levels 5-9.
#pragma unroll
    for (int l = 5; l < NLVL; l++) {
        const __half* gp = g_tab + ((size_t)(idx[l] + 2)) * EMB + qi * 8;
        asm volatile("cp.async.cg.shared.global [%0], [%1], 16;"
                     :: "r"(sbase + l * (EMB * 2)), "l"(gp));
    }
    asm volatile("cp.async.commit_group;");

    // Alphas: fast path = prenormalized g_al. Slow path only if some idx == -2.
    bool bad = false;
#pragma unroll
    for (int l = 0; l < NLVL; l++) bad |= (idx[l] == -2);

    const float4 aa = *reinterpret_cast<const float4*>(&g_al[0]);
    const float4 ab = *reinterpret_cast<const float4*>(&g_al[4]);
    const float2 ac = *reinterpret_cast<const float2*>(&g_al[8]);
    float al[NLVL] = { aa.x, aa.y, aa.z, aa.w,
                       ab.x, ab.y, ab.z, ab.w, ac.x, ac.y };
    if (__builtin_expect(bad, 0)) {
        const float4 ea = *reinterpret_cast<const float4*>(&g_ew[0]);
        const float4 eb = *reinterpret_cast<const float4*>(&g_ew[4]);
        const float2 ec = *reinterpret_cast<const float2*>(&g_ew[8]);
        const float e[NLVL] = { ea.x, ea.y, ea.z, ea.w,
                                eb.x, eb.y, eb.z, eb.w, ec.x, ec.y };
        float s = 0.0f;
#pragma unroll
        for (int l = 0; l < NLVL; l++) s += (idx[l] != -2) ? e[l] : 0.0f;
        const float inv = (s > 0.0f) ? __frcp_rn(s) : 0.0f;
#pragma unroll
        for (int l = 0; l < NLVL; l++)
            al[l] = (idx[l] != -2) ? e[l] * inv : 0.0f;
    }

    float acc[8] = {0.f,0.f,0.f,0.f,0.f,0.f,0.f,0.f};

    asm volatile("cp.async.wait_group 1;");
    __syncwarp();
#pragma unroll
    for (int l = 0; l < 5; l++) {
        const uint4 v = *reinterpret_cast<const uint4*>(&stab[wid][tw][l][qi * 8]);
        const float2 a = __half22float2(*reinterpret_cast<const __half2*>(&v.x));
        const float2 b = __half22float2(*reinterpret_cast<const __half2*>(&v.y));
        const float2 c = __half22float2(*reinterpret_cast<const __half2*>(&v.z));
        const float2 d = __half22float2(*reinterpret_cast<const __half2*>(&v.w));
        acc[0] = fmaf(al[l], a.x, acc[0]);
        acc[1] = fmaf(al[l], a.y, acc[1]);
        acc[2] = fmaf(al[l], b.x, acc[2]);
        acc[3] = fmaf(al[l], b.y, acc[3]);
        acc[4] = fmaf(al[l], c.x, acc[4]);
        acc[5] = fmaf(al[l], c.y, acc[5]);
        acc[6] = fmaf(al[l], d.x, acc[6]);
        acc[7] = fmaf(al[l], d.y, acc[7]);
    }

    asm volatile("cp.async.wait_group 0;");
    __syncwarp();
#pragma unroll
    for (int l = 5; l < NLVL; l++) {
        const uint4 v = *reinterpret_cast<const uint4*>(&stab[wid][tw][l][qi * 8]);
        const float2 a = __half22float2(*reinterpret_cast<const __half2*>(&v.x));
        const float2 b = __half22float2(*reinterpret_cast<const __half2*>(&v.y));
        const float2 c = __half22float2(*reinterpret_cast<const __half2*>(&v.z));
        const float2 d = __half22float2(*reinterpret_cast<const __half2*>(&v.w));
        acc[0] = fmaf(al[l], a.x, acc[0]);
        acc[1] = fmaf(al[l], a.y, acc[1]);
        acc[2] = fmaf(al[l], b.x, acc[2]);
        acc[3] = fmaf(al[l], b.y, acc[3]);
        acc[4] = fmaf(al[l], c.x, acc[4]);
        acc[5] = fmaf(al[l], c.y, acc[5]);
        acc[6] = fmaf(al[l], d.x, acc[6]);
        acc[7] = fmaf(al[l], d.y, acc[7]);
    }

    if (valid) {
        float* op = out + (size_t)tok * EMB + qi * 8;
        *reinterpret_cast<float4*>(op) =
            make_float4(acc[0], acc[1], acc[2], acc[3]);
        *reinterpret_cast<float4*>(op + 4) =
            make_float4(acc[4], acc[5], acc[6], acc[7]);
    }
}

extern "C" void kernel_launch(void* const* d_in, const int* in_sizes, int n_in,
                              void* d_out, int out_size) {
    const int*   croutes = (const int*)d_in[0];
    // d_in[1] (tailcs) unused by the reference computation.
    const float* emb     = (const float*)d_in[2];
    const float* w       = (const float*)d_in[3];
    float*       out     = (float*)d_out;

    const int ntok = in_sizes[1];                 // B * S
    const int n16  = in_sizes[2] / 16;            // table 16-float chunks
    conv_kernel<<<(n16 + 255) / 256, 256>>>(emb, w, n16);

    const int blocks = (ntok + 31) / 32;          // 32 tokens per 256-thread block

    cudaLaunchConfig_t cfg = {};
    cfg.gridDim  = dim3((unsigned)blocks, 1, 1);
    cfg.blockDim = dim3(256, 1, 1);
    cudaLaunchAttribute attr[1];
    attr[0].id = cudaLaunchAttributeProgrammaticStreamSerialization;
    attr[0].val.programmaticStreamSerializationAllowed = 1;
    cfg.attrs    = attr;
    cfg.numAttrs = 1;
    cudaError_t err = cudaLaunchKernelEx(&cfg, kcroute_kernel, croutes, out, ntok);
    if (err != cudaSuccess) {
        kcroute_kernel<<<blocks, 256>>>(croutes, out, ntok);
    }
}